// round 14
// baseline (speedup 1.0000x reference)
#include <cuda_runtime.h>
#include <cstdint>
#include <math.h>

// Problem constants
#define N_ROWS 8192
#define D_DIM  64
#define B_HALF 1024          // epsilon = [tmp; -tmp] antisymmetry folds B=2048 -> 1024
#define TWO_PI 6.283185307179586f
#define INV_TWO_PI 0.15915494309189535f

// Tiling: block = 256 rows x 64 basis; thread = 16 rows x 4 basis
// lane-bytes/FFMA2 = 8(R+C)/(RC) = 2.5 (vs 3.0 in the 8x4 champion)
#define TBM 256              // main threads per block
#define ROWS_T 256           // rows per block (128 rowpairs)
#define BT 64                // basis per block
#define NG (B_HALF / BT)     // 16 b-groups

// Shared layout
#define SX_STRIDE 260        // floats per k-row of x tile (= 130 u64, even)
#define SS_STRIDE 68         // floats per k-row of s tile
#define SU_STRIDE 130        // u64 per b-row of U tile (even -> ulonglong2 loads)
#define OFF_X  0
#define OFF_S  (64 * SX_STRIDE * 4)                 // 66560
#define OFF_W  (OFF_S + 64 * SS_STRIDE * 4)         // 83968
#define SMEM_BYTES (OFF_W + 2 * BT * 4)             // 84480
// U tile alias: 64 * 130 * 8 = 66560 == OFF_S  ✓

typedef unsigned long long u64;

// Packed f32x2 math (Blackwell FFMA2)
#define FMA2(d, a, b, c) asm("fma.rn.f32x2 %0, %1, %2, %3;" : "=l"(d) : "l"(a), "l"(b), "l"(c))
#define PACK2(d, lo, hi) asm("mov.b64 %0, {%1, %2};"        : "=l"(d) : "f"(lo), "f"(hi))
#define UNPACK2(lo, hi, s) asm("mov.b64 {%0, %1}, %2;"      : "=f"(lo), "=f"(hi) : "l"(s))

// Vector float atomic-add, no return (REDG.128). sm_90+.
#define RED_ADD_V4(ptr, a, b, c, d) \
    asm volatile("red.global.add.v4.f32 [%0], {%1, %2, %3, %4};" \
                 :: "l"(ptr), "f"(a), "f"(b), "f"(c), "f"(d) : "memory")

// Device scratch
__device__ float g_S[B_HALF * D_DIM];     // s[b][j] = eps[b][j] / (2*pi*lam[j])
__device__ float g_M[B_HALF * D_DIM];     // mat[b][i]
__device__ float g_R[B_HALF];             // sqrt(ws^2 + wc^2)
__device__ float g_P[B_HALF];             // atan2(wc, ws) / (2*pi)

// ---------------------------------------------------------------------------
// Precompute S, mat, phase-identity weights; zero the output (REDG target).
// ---------------------------------------------------------------------------
__global__ void prep_kernel(const float* __restrict__ eps,
                            const float* __restrict__ lam,
                            const float* __restrict__ eta,
                            const float* __restrict__ w,
                            float4* __restrict__ out) {
    int idx = blockIdx.x * blockDim.x + threadIdx.x;
    if (idx < B_HALF * D_DIM) {
        int b = idx >> 6;
        int j = idx & 63;
        float l = lam[j];
        g_S[idx] = eps[idx] / (TWO_PI * l);
        float eta2 = eta[0] * eta[0];
        float m;
        if (j < 32) {
            m = eps[b * 64 + 32 + j] / lam[32 + j];
        } else {
            m = -eps[b * 64 + (j - 32)] / lam[j - 32] - eta2 * eps[idx] / l;
        }
        g_M[idx] = m;
    }
    if (idx < B_HALF) {
        float ws = -(w[idx] + w[idx + B_HALF]);
        float wc = w[2 * B_HALF + idx] - w[3 * B_HALF + idx];
        g_R[idx] = sqrtf(ws * ws + wc * wc);
        g_P[idx] = atan2f(wc, ws) * INV_TWO_PI;
    }
    // Zero output: 131072 float4 across 65536 threads -> 2 each
    out[idx]         = make_float4(0.f, 0.f, 0.f, 0.f);
    out[idx + 65536] = make_float4(0.f, 0.f, 0.f, 0.f);
}

// ---------------------------------------------------------------------------
// Main fused kernel. 16x4 per-thread tiles (8 rowpairs x 4 basis/dims) cut
// smem lane-bytes per FFMA2 from 3.0 to 2.5 while keeping acc at 64 regs.
// Thread (ty = tid/16, tx = tid%16):
//   Phase A: 16 rows (rowpairs 8ty..+7) x 4 basis (4tx..+3)
//   Phase B: 16 rows x 4 dims (4tx..+3), K = 64 basis of this group
// ---------------------------------------------------------------------------
__global__ void __launch_bounds__(TBM, 2)
main_kernel(const float* __restrict__ x, float* __restrict__ out) {
    extern __shared__ char smem[];
    float* sXf = (float*)(smem + OFF_X);   // [64 k][SX_STRIDE]  x transposed
    float* sSf = (float*)(smem + OFF_S);   // [64 k][SS_STRIDE]  s transposed
    float* sW  = (float*)(smem + OFF_W);   // [2*BT] interleaved R/phi
    u64*   sUu = (u64*)(smem + OFF_X);     // alias: [64 b][SU_STRIDE] U rowpairs
    float* sMf = (float*)(smem + OFF_S);   // alias: [64 b][64] M tile

    const int tid = threadIdx.x;
    const int ty  = tid >> 4;              // 0..15
    const int tx  = tid & 15;              // 0..15
    const int bx  = blockIdx.x;
    const int g   = blockIdx.y;
    const int b0  = g * BT;

    // ---- Stage x/s tiles transposed into shared memory ----
    {
        const float4* xg = (const float4*)(x + (size_t)bx * ROWS_T * D_DIM);
        #pragma unroll
        for (int it = 0; it < 16; ++it) {
            int i  = tid + it * TBM;       // float4 id, 4096 total
            int r  = i >> 4;               // row 0..255
            int k4 = (i & 15) * 4;
            float4 v = xg[i];
            sXf[(k4 + 0) * SX_STRIDE + r] = v.x;
            sXf[(k4 + 1) * SX_STRIDE + r] = v.y;
            sXf[(k4 + 2) * SX_STRIDE + r] = v.z;
            sXf[(k4 + 3) * SX_STRIDE + r] = v.w;
        }
        const float4* sg = (const float4*)(g_S + (size_t)b0 * D_DIM);
        #pragma unroll
        for (int it = 0; it < 4; ++it) {
            int i  = tid + it * TBM;       // float4 id, 1024 total
            int b  = i >> 4;
            int k4 = (i & 15) * 4;
            float4 v = sg[i];
            sSf[(k4 + 0) * SS_STRIDE + b] = v.x;
            sSf[(k4 + 1) * SS_STRIDE + b] = v.y;
            sSf[(k4 + 2) * SS_STRIDE + b] = v.z;
            sSf[(k4 + 3) * SS_STRIDE + b] = v.w;
        }
        if (tid < BT) {
            sW[2 * tid]     = g_R[b0 + tid];
            sW[2 * tid + 1] = g_P[b0 + tid];
        }
    }
    __syncthreads();

    // ---- Phase A: sim tile. acc[i=b_local 0..3][j=rowpair 0..7] ----
    u64 acc[4][8];
    #pragma unroll
    for (int i = 0; i < 4; ++i)
        #pragma unroll
        for (int j = 0; j < 8; ++j) acc[i][j] = 0ull;

    {
        const u64*   xb = (const u64*)sXf + 8 * ty;   // rowpairs 8ty..8ty+7
        const float* sb = sSf + 4 * tx;               // basis 4*tx .. +3
        #pragma unroll 2
        for (int k = 0; k < 64; ++k) {
            ulonglong2 xa = *(const ulonglong2*)(xb + k * (SX_STRIDE / 2));
            ulonglong2 xbv = *(const ulonglong2*)(xb + k * (SX_STRIDE / 2) + 2);
            ulonglong2 xc = *(const ulonglong2*)(xb + k * (SX_STRIDE / 2) + 4);
            ulonglong2 xd = *(const ulonglong2*)(xb + k * (SX_STRIDE / 2) + 6);
            u64 xv[8];
            xv[0] = xa.x;  xv[1] = xa.y;  xv[2] = xbv.x; xv[3] = xbv.y;
            xv[4] = xc.x;  xv[5] = xc.y;  xv[6] = xd.x;  xv[7] = xd.y;
            float4 sv = *(const float4*)(sb + k * SS_STRIDE);
            u64 s0, s1, s2, s3;
            PACK2(s0, sv.x, sv.x);
            PACK2(s1, sv.y, sv.y);
            PACK2(s2, sv.z, sv.z);
            PACK2(s3, sv.w, sv.w);
            #pragma unroll
            for (int j = 0; j < 8; ++j) {
                FMA2(acc[0][j], xv[j], s0, acc[0][j]);
                FMA2(acc[1][j], xv[j], s1, acc[1][j]);
                FMA2(acc[2][j], xv[j], s2, acc[2][j]);
                FMA2(acc[3][j], xv[j], s3, acc[3][j]);
            }
        }
    }

    // ---- Epilogue: u = R * sin(2*pi*frac(p + phi2pi))  (1 MUFU/value) ----
    #pragma unroll
    for (int i = 0; i < 4; ++i) {
        int bl = tx * 4 + i;
        float R  = sW[2 * bl];
        float ph = sW[2 * bl + 1];
        #pragma unroll
        for (int j = 0; j < 8; ++j) {
            float p0, p1;
            UNPACK2(p0, p1, acc[i][j]);
            p0 += ph;
            p1 += ph;
            float r0 = p0 - rintf(p0);
            float r1 = p1 - rintf(p1);
            float u0 = R * __sinf(r0 * TWO_PI);
            float u1 = R * __sinf(r1 * TWO_PI);
            PACK2(acc[i][j], u0, u1);
        }
    }

    __syncthreads();   // all shared reads of sXf/sSf done before aliasing

    // ---- Write U tile (rowpair-packed) + stage M tile into aliased smem ----
    #pragma unroll
    for (int i = 0; i < 4; ++i) {
        int bl = tx * 4 + i;
        #pragma unroll
        for (int j = 0; j < 8; ++j) {
            sUu[bl * SU_STRIDE + ty * 8 + j] = acc[i][j];
        }
    }
    {
        const float4* mg = (const float4*)(g_M + (size_t)b0 * D_DIM);
        float4* md = (float4*)sMf;
        #pragma unroll
        for (int it = 0; it < 4; ++it) {
            int i = tid + it * TBM;
            md[i] = mg[i];
        }
    }
    __syncthreads();

    // ---- Phase B: f_partial = U @ M.  o[j=rowpair 0..7][i=d_local 0..3] ----
    u64 o[8][4];
    #pragma unroll
    for (int j = 0; j < 8; ++j)
        #pragma unroll
        for (int i = 0; i < 4; ++i) o[j][i] = 0ull;

    {
        const u64*   ubase = sUu + 8 * ty;
        const float* mbase = sMf + 4 * tx;
        #pragma unroll 2
        for (int b = 0; b < 64; ++b) {
            ulonglong2 ua = *(const ulonglong2*)(ubase + b * SU_STRIDE);
            ulonglong2 ub2 = *(const ulonglong2*)(ubase + b * SU_STRIDE + 2);
            ulonglong2 uc = *(const ulonglong2*)(ubase + b * SU_STRIDE + 4);
            ulonglong2 ud = *(const ulonglong2*)(ubase + b * SU_STRIDE + 6);
            u64 uv[8];
            uv[0] = ua.x;  uv[1] = ua.y;  uv[2] = ub2.x; uv[3] = ub2.y;
            uv[4] = uc.x;  uv[5] = uc.y;  uv[6] = ud.x;  uv[7] = ud.y;
            float4 mv = *(const float4*)(mbase + b * 64);
            u64 m0, m1, m2, m3;
            PACK2(m0, mv.x, mv.x);
            PACK2(m1, mv.y, mv.y);
            PACK2(m2, mv.z, mv.z);
            PACK2(m3, mv.w, mv.w);
            #pragma unroll
            for (int j = 0; j < 8; ++j) {
                FMA2(o[j][0], uv[j], m0, o[j][0]);
                FMA2(o[j][1], uv[j], m1, o[j][1]);
                FMA2(o[j][2], uv[j], m2, o[j][2]);
                FMA2(o[j][3], uv[j], m3, o[j][3]);
            }
        }
    }

    // ---- Accumulate directly into output via vector REDG ----
    {
        float* obase = out + (size_t)bx * ROWS_T * D_DIM;
        #pragma unroll
        for (int j = 0; j < 8; ++j) {
            float4 lo, hi;
            UNPACK2(lo.x, hi.x, o[j][0]);
            UNPACK2(lo.y, hi.y, o[j][1]);
            UNPACK2(lo.z, hi.z, o[j][2]);
            UNPACK2(lo.w, hi.w, o[j][3]);
            int row = 16 * ty + 2 * j;
            float* p0 = obase + (size_t)row * D_DIM + 4 * tx;
            float* p1 = obase + (size_t)(row + 1) * D_DIM + 4 * tx;
            RED_ADD_V4(p0, lo.x, lo.y, lo.z, lo.w);
            RED_ADD_V4(p1, hi.x, hi.y, hi.z, hi.w);
        }
    }
}

// ---------------------------------------------------------------------------
extern "C" void kernel_launch(void* const* d_in, const int* in_sizes, int n_in,
                              void* d_out, int out_size) {
    const float* x   = nullptr;
    const float* eps = nullptr;
    const float* lam = nullptr;
    const float* eta = nullptr;
    const float* w   = nullptr;
    int ones_seen = 0;
    for (int i = 0; i < n_in; ++i) {
        int sz = in_sizes[i];
        const float* p = (const float*)d_in[i];
        if      (sz == N_ROWS * D_DIM)     x   = p;
        else if (sz == 2 * B_HALF * D_DIM) eps = p;
        else if (sz == D_DIM)              lam = p;
        else if (sz == 4 * B_HALF)         w   = p;
        else if (sz == 1) {
            if (ones_seen == 1) eta = p;   // second size-1 input is eta
            ones_seen++;
        }
    }

    cudaFuncSetAttribute(main_kernel,
                         cudaFuncAttributeMaxDynamicSharedMemorySize, SMEM_BYTES);

    prep_kernel<<<(B_HALF * D_DIM + 255) / 256, 256>>>(eps, lam, eta, w,
                                                       (float4*)d_out);
    main_kernel<<<dim3(N_ROWS / ROWS_T, NG), TBM, SMEM_BYTES>>>(x, (float*)d_out);
}

// round 16
// speedup vs baseline: 1.6645x; 1.6645x over previous
#include <cuda_runtime.h>
#include <cuda_bf16.h>
#include <cstdint>
#include <math.h>

// Problem constants
#define N_ROWS 8192
#define D_DIM  64
#define B_HALF 1024          // epsilon = [tmp; -tmp] antisymmetry folds B=2048 -> 1024
#define TWO_PI 6.283185307179586f
#define INV_TWO_PI 0.15915494309189535f

#define TBM 256              // 8 warps: each owns 16 rows of the 128-row tile

// Shared tiles, bf16, row stride 72 (pad: fragment loads hit all 32 banks)
#define XST 72               // X/U tile stride (rows 128)
#define SST 72               // S/Mt tile stride (rows 64)
#define OFF_XHI 0
#define OFF_XLO (OFF_XHI + 128 * XST * 2)    // 18432
#define OFF_SHI (OFF_XLO + 128 * XST * 2)    // 36864
#define OFF_SLO (OFF_SHI + 64 * SST * 2)     // 46080
#define OFF_MTH (OFF_SLO + 64 * SST * 2)     // 55296
#define OFF_MTL (OFF_MTH + 64 * SST * 2)     // 64512
#define OFF_R   (OFF_MTL + 64 * SST * 2)     // 73728
#define OFF_P   (OFF_R + 256)
#define SMEM_BYTES (OFF_P + 256)             // 74240

typedef unsigned int u32;

// Warp MMA: D(16x8,f32) += A(16x16 bf16 row) * B(16x8 bf16 col)
#define MMA_BF16(c, a, b) \
    asm volatile("mma.sync.aligned.m16n8k16.row.col.f32.bf16.bf16.f32 " \
        "{%0,%1,%2,%3}, {%4,%5,%6,%7}, {%8,%9}, {%0,%1,%2,%3};" \
        : "+f"((c)[0]), "+f"((c)[1]), "+f"((c)[2]), "+f"((c)[3]) \
        : "r"((a)[0]), "r"((a)[1]), "r"((a)[2]), "r"((a)[3]), \
          "r"((b)[0]), "r"((b)[1]))

#define RED_ADD_V2(ptr, a, b) \
    asm volatile("red.global.add.v2.f32 [%0], {%1, %2};" \
                 :: "l"(ptr), "f"(a), "f"(b) : "memory")

__device__ __forceinline__ u32 pack_bf16(float lo, float hi) {
    __nv_bfloat16 a = __float2bfloat16(lo);
    __nv_bfloat16 b = __float2bfloat16(hi);
    return (u32)__bfloat16_as_ushort(a) | ((u32)__bfloat16_as_ushort(b) << 16);
}

// Device scratch: bf16 split operands + phase-identity weights
__device__ __nv_bfloat16 g_Shi[B_HALF * D_DIM];   // s hi, [b][j]
__device__ __nv_bfloat16 g_Slo[B_HALF * D_DIM];   // s lo
__device__ __nv_bfloat16 g_Mthi[D_DIM * B_HALF];  // M^T hi, [d][b]
__device__ __nv_bfloat16 g_Mtlo[D_DIM * B_HALF];  // M^T lo
__device__ float g_R[B_HALF];
__device__ float g_P[B_HALF];

// ---------------------------------------------------------------------------
// Prep: split s and M^T into bf16 hi/lo, phase-identity weights, zero output.
// ---------------------------------------------------------------------------
__global__ void prep_kernel(const float* __restrict__ eps,
                            const float* __restrict__ lam,
                            const float* __restrict__ eta,
                            const float* __restrict__ w,
                            float4* __restrict__ out) {
    int idx = blockIdx.x * blockDim.x + threadIdx.x;
    if (idx < B_HALF * D_DIM) {
        int b = idx >> 6;
        int j = idx & 63;
        float l = lam[j];
        float s = eps[idx] / (TWO_PI * l);
        __nv_bfloat16 sh = __float2bfloat16(s);
        g_Shi[idx] = sh;
        g_Slo[idx] = __float2bfloat16(s - __bfloat162float(sh));
        float eta2 = eta[0] * eta[0];
        float m;
        if (j < 32) {
            m = eps[b * 64 + 32 + j] / lam[32 + j];
        } else {
            m = -eps[b * 64 + (j - 32)] / lam[j - 32] - eta2 * eps[idx] / l;
        }
        __nv_bfloat16 mh = __float2bfloat16(m);
        g_Mthi[j * B_HALF + b] = mh;
        g_Mtlo[j * B_HALF + b] = __float2bfloat16(m - __bfloat162float(mh));
    }
    if (idx < B_HALF) {
        float ws = -(w[idx] + w[idx + B_HALF]);
        float wc = w[2 * B_HALF + idx] - w[3 * B_HALF + idx];
        g_R[idx] = sqrtf(ws * ws + wc * wc);
        g_P[idx] = atan2f(wc, ws) * INV_TWO_PI;
    }
    out[idx]         = make_float4(0.f, 0.f, 0.f, 0.f);
    out[idx + 65536] = make_float4(0.f, 0.f, 0.f, 0.f);
}

// ---------------------------------------------------------------------------
// Main kernel: warp-level bf16 MMA (m16n8k16), split precision (3 MMAs per
// product). Block = 128 rows x 64 basis (grid 64 x 16); REDG merges groups.
// Fragment roles per lane (g = lane/4, t = lane%4):
//   A: rows {g, g+8} of warp's 16-row slab, k = {2t,2t+1} (+8)
//   B: k = {2t,2t+1} (+8), col n = g
//   C: rows {g, g+8}, cols {2t, 2t+1}
// ---------------------------------------------------------------------------
__global__ void __launch_bounds__(TBM, 2)
main_kernel(const float* __restrict__ x, float* __restrict__ out) {
    extern __shared__ char smem[];
    u32* xhi32 = (u32*)(smem + OFF_XHI);   // [128][XST] bf16 -> u32 idx row*36+kp
    u32* xlo32 = (u32*)(smem + OFF_XLO);
    u32* shi32 = (u32*)(smem + OFF_SHI);   // [64][SST]  bf16 -> u32 idx b*36+jp
    u32* slo32 = (u32*)(smem + OFF_SLO);
    u32* mth32 = (u32*)(smem + OFF_MTH);   // [64 d][SST] over b
    u32* mtl32 = (u32*)(smem + OFF_MTL);
    float* sR  = (float*)(smem + OFF_R);
    float* sP  = (float*)(smem + OFF_P);
    u32* uhi32 = xhi32;                    // U tile aliases X tile (phase B)
    u32* ulo32 = xlo32;

    const int tid  = threadIdx.x;
    const int lane = tid & 31;
    const int wr   = (tid >> 5) * 16;      // warp's first row
    const int g    = lane >> 2;            // 0..7
    const int t    = lane & 3;             // 0..3
    const int bx   = blockIdx.x;
    const int b0   = blockIdx.y * 64;

    // ---- Stage X (f32 -> bf16 hi/lo), S, Mt tiles, R/phi ----
    {
        const float2* xg = (const float2*)(x + (size_t)bx * 128 * D_DIM);
        #pragma unroll
        for (int it = 0; it < 16; ++it) {
            int i   = tid + it * TBM;      // pair id, 4096 total
            int row = i >> 5;
            int kp  = i & 31;
            float2 v = xg[i];
            __nv_bfloat16 h0 = __float2bfloat16(v.x);
            __nv_bfloat16 h1 = __float2bfloat16(v.y);
            float l0 = v.x - __bfloat162float(h0);
            float l1 = v.y - __bfloat162float(h1);
            xhi32[row * 36 + kp] =
                (u32)__bfloat16_as_ushort(h0) | ((u32)__bfloat16_as_ushort(h1) << 16);
            xlo32[row * 36 + kp] = pack_bf16(l0, l1);
        }
        const u32* gShi = (const u32*)g_Shi;
        const u32* gSlo = (const u32*)g_Slo;
        const u32* gMth = (const u32*)g_Mthi;
        const u32* gMtl = (const u32*)g_Mtlo;
        #pragma unroll
        for (int it = 0; it < 8; ++it) {
            int i = tid + it * TBM;        // pair id, 2048 total
            int r = i >> 5;                // basis row (S) / dim row (Mt)
            int p = i & 31;
            shi32[r * 36 + p] = gShi[(b0 + r) * 32 + p];
            slo32[r * 36 + p] = gSlo[(b0 + r) * 32 + p];
            mth32[r * 36 + p] = gMth[r * 512 + (b0 >> 1) + p];
            mtl32[r * 36 + p] = gMtl[r * 512 + (b0 >> 1) + p];
        }
        if (tid < 64) {
            sR[tid] = g_R[b0 + tid];
            sP[tid] = g_P[b0 + tid];
        }
    }
    __syncthreads();

    // ---- Phase A: P = Xhi@Shi^T + Xlo@Shi^T + Xhi@Slo^T ----
    float pA[8][4];
    #pragma unroll
    for (int nt = 0; nt < 8; ++nt)
        #pragma unroll
        for (int c = 0; c < 4; ++c) pA[nt][c] = 0.0f;

    {
        const int rA  = (wr + g) * 36;
        const int rA8 = (wr + g + 8) * 36;
        #pragma unroll
        for (int ks = 0; ks < 4; ++ks) {
            int kh = ks * 8 + t;
            u32 ah[4], al[4];
            ah[0] = xhi32[rA + kh];      ah[1] = xhi32[rA8 + kh];
            ah[2] = xhi32[rA + kh + 4];  ah[3] = xhi32[rA8 + kh + 4];
            al[0] = xlo32[rA + kh];      al[1] = xlo32[rA8 + kh];
            al[2] = xlo32[rA + kh + 4];  al[3] = xlo32[rA8 + kh + 4];
            #pragma unroll
            for (int nt = 0; nt < 8; ++nt) {
                int nb = (nt * 8 + g) * 36;
                u32 bh[2] = { shi32[nb + kh], shi32[nb + kh + 4] };
                u32 bl[2] = { slo32[nb + kh], slo32[nb + kh + 4] };
                MMA_BF16(pA[nt], ah, bh);
                MMA_BF16(pA[nt], al, bh);
                MMA_BF16(pA[nt], ah, bl);
            }
        }
    }
    __syncthreads();   // all phase-A smem reads done before U aliases X

    // ---- Epilogue: u = R*sin(2*pi*frac(p + phi)); split bf16 -> U tile ----
    #pragma unroll
    for (int nt = 0; nt < 8; ++nt) {
        int c0 = nt * 8 + 2 * t;
        float R0 = sR[c0], R1 = sR[c0 + 1];
        float P0 = sP[c0], P1 = sP[c0 + 1];
        float p00 = pA[nt][0] + P0, p01 = pA[nt][1] + P1;
        float p10 = pA[nt][2] + P0, p11 = pA[nt][3] + P1;
        float u00 = R0 * __sinf((p00 - rintf(p00)) * TWO_PI);
        float u01 = R1 * __sinf((p01 - rintf(p01)) * TWO_PI);
        float u10 = R0 * __sinf((p10 - rintf(p10)) * TWO_PI);
        float u11 = R1 * __sinf((p11 - rintf(p11)) * TWO_PI);
        __nv_bfloat16 h00 = __float2bfloat16(u00);
        __nv_bfloat16 h01 = __float2bfloat16(u01);
        __nv_bfloat16 h10 = __float2bfloat16(u10);
        __nv_bfloat16 h11 = __float2bfloat16(u11);
        int ilo = (wr + g) * 36 + nt * 4 + t;
        int ihi = (wr + g + 8) * 36 + nt * 4 + t;
        uhi32[ilo] = (u32)__bfloat16_as_ushort(h00) | ((u32)__bfloat16_as_ushort(h01) << 16);
        uhi32[ihi] = (u32)__bfloat16_as_ushort(h10) | ((u32)__bfloat16_as_ushort(h11) << 16);
        ulo32[ilo] = pack_bf16(u00 - __bfloat162float(h00), u01 - __bfloat162float(h01));
        ulo32[ihi] = pack_bf16(u10 - __bfloat162float(h10), u11 - __bfloat162float(h11));
    }
    __syncthreads();

    // ---- Phase B: F = Uhi@Mthi^T + Ulo@Mthi^T + Uhi@Mtlo^T ----
    float fB[8][4];
    #pragma unroll
    for (int nt = 0; nt < 8; ++nt)
        #pragma unroll
        for (int c = 0; c < 4; ++c) fB[nt][c] = 0.0f;

    {
        const int rA  = (wr + g) * 36;
        const int rA8 = (wr + g + 8) * 36;
        #pragma unroll
        for (int ks = 0; ks < 4; ++ks) {
            int kh = ks * 8 + t;
            u32 ah[4], al[4];
            ah[0] = uhi32[rA + kh];      ah[1] = uhi32[rA8 + kh];
            ah[2] = uhi32[rA + kh + 4];  ah[3] = uhi32[rA8 + kh + 4];
            al[0] = ulo32[rA + kh];      al[1] = ulo32[rA8 + kh];
            al[2] = ulo32[rA + kh + 4];  al[3] = ulo32[rA8 + kh + 4];
            #pragma unroll
            for (int nt = 0; nt < 8; ++nt) {
                int nb = (nt * 8 + g) * 36;
                u32 bh[2] = { mth32[nb + kh], mth32[nb + kh + 4] };
                u32 bl[2] = { mtl32[nb + kh], mtl32[nb + kh + 4] };
                MMA_BF16(fB[nt], ah, bh);
                MMA_BF16(fB[nt], al, bh);
                MMA_BF16(fB[nt], ah, bl);
            }
        }
    }

    // ---- Accumulate into output via vector REDG ----
    {
        float* ob = out + (size_t)bx * 128 * D_DIM;
        #pragma unroll
        for (int nt = 0; nt < 8; ++nt) {
            int col = nt * 8 + 2 * t;
            float* plo = ob + (size_t)(wr + g) * D_DIM + col;
            float* phi = ob + (size_t)(wr + g + 8) * D_DIM + col;
            RED_ADD_V2(plo, fB[nt][0], fB[nt][1]);
            RED_ADD_V2(phi, fB[nt][2], fB[nt][3]);
        }
    }
}

// ---------------------------------------------------------------------------
extern "C" void kernel_launch(void* const* d_in, const int* in_sizes, int n_in,
                              void* d_out, int out_size) {
    const float* x   = nullptr;
    const float* eps = nullptr;
    const float* lam = nullptr;
    const float* eta = nullptr;
    const float* w   = nullptr;
    int ones_seen = 0;
    for (int i = 0; i < n_in; ++i) {
        int sz = in_sizes[i];
        const float* p = (const float*)d_in[i];
        if      (sz == N_ROWS * D_DIM)     x   = p;
        else if (sz == 2 * B_HALF * D_DIM) eps = p;
        else if (sz == D_DIM)              lam = p;
        else if (sz == 4 * B_HALF)         w   = p;
        else if (sz == 1) {
            if (ones_seen == 1) eta = p;   // second size-1 input is eta
            ones_seen++;
        }
    }

    cudaFuncSetAttribute(main_kernel,
                         cudaFuncAttributeMaxDynamicSharedMemorySize, SMEM_BYTES);

    prep_kernel<<<(B_HALF * D_DIM + 255) / 256, 256>>>(eps, lam, eta, w,
                                                       (float4*)d_out);
    main_kernel<<<dim3(N_ROWS / 128, B_HALF / 64), TBM, SMEM_BYTES>>>(
        x, (float*)d_out);
}

// round 17
// speedup vs baseline: 1.8561x; 1.1151x over previous
#include <cuda_runtime.h>
#include <cuda_bf16.h>
#include <cstdint>
#include <math.h>

// Problem constants
#define N_ROWS 8192
#define D_DIM  64
#define B_HALF 1024          // epsilon = [tmp; -tmp] antisymmetry folds B=2048 -> 1024
#define TWO_PI 6.283185307179586f
#define INV_TWO_PI 0.15915494309189535f

#define TBM 256              // 8 warps: each owns 16 rows of the 128-row tile

// Shared tiles, bf16, row stride 72 b16 = 36 u32 (rows hit distinct bank groups)
#define XST 72
#define SST 72
#define OFF_XHI 0
#define OFF_XLO (OFF_XHI + 128 * XST * 2)    // 18432
#define OFF_SHI (OFF_XLO + 128 * XST * 2)    // 36864
#define OFF_SLO (OFF_SHI + 64 * SST * 2)     // 46080
#define OFF_MTH (OFF_SLO + 64 * SST * 2)     // 55296
#define OFF_MTL (OFF_MTH + 64 * SST * 2)     // 64512
#define OFF_R   (OFF_MTL + 64 * SST * 2)     // 73728
#define OFF_P   (OFF_R + 256)
#define SMEM_BYTES (OFF_P + 256)             // 74240

typedef unsigned int u32;

// Warp MMA: D(16x8,f32) += A(16x16 bf16 row) * B(16x8 bf16 col)
#define MMA_BF16(c, a, b) \
    asm volatile("mma.sync.aligned.m16n8k16.row.col.f32.bf16.bf16.f32 " \
        "{%0,%1,%2,%3}, {%4,%5,%6,%7}, {%8,%9}, {%0,%1,%2,%3};" \
        : "+f"((c)[0]), "+f"((c)[1]), "+f"((c)[2]), "+f"((c)[3]) \
        : "r"((a)[0]), "r"((a)[1]), "r"((a)[2]), "r"((a)[3]), \
          "r"((b)[0]), "r"((b)[1]))

// ldmatrix: 4x 8x8 b16 tiles; lane l gets (row=l/4, colpair=l%4) of each tile
#define LDSM_X4(r, addr) \
    asm volatile("ldmatrix.sync.aligned.m8n8.x4.shared.b16 {%0,%1,%2,%3}, [%4];" \
        : "=r"((r)[0]), "=r"((r)[1]), "=r"((r)[2]), "=r"((r)[3]) : "r"(addr))

#define RED_ADD_V2(ptr, a, b) \
    asm volatile("red.global.add.v2.f32 [%0], {%1, %2};" \
                 :: "l"(ptr), "f"(a), "f"(b) : "memory")

__device__ __forceinline__ u32 smem_to_u32(const void* p) {
    u32 a;
    asm("{ .reg .u64 t; cvta.to.shared.u64 t, %1; cvt.u32.u64 %0, t; }"
        : "=r"(a) : "l"(p));
    return a;
}

__device__ __forceinline__ u32 pack_bf16(float lo, float hi) {
    __nv_bfloat16 a = __float2bfloat16(lo);
    __nv_bfloat16 b = __float2bfloat16(hi);
    return (u32)__bfloat16_as_ushort(a) | ((u32)__bfloat16_as_ushort(b) << 16);
}

// Device scratch: bf16 split operands + phase-identity weights
__device__ __nv_bfloat16 g_Shi[B_HALF * D_DIM];   // s hi, [b][j]
__device__ __nv_bfloat16 g_Slo[B_HALF * D_DIM];   // s lo
__device__ __nv_bfloat16 g_Mthi[D_DIM * B_HALF];  // M^T hi, [d][b]
__device__ __nv_bfloat16 g_Mtlo[D_DIM * B_HALF];  // M^T lo
__device__ float g_R[B_HALF];
__device__ float g_P[B_HALF];

// ---------------------------------------------------------------------------
// Prep: split s and M^T into bf16 hi/lo, phase-identity weights, zero output.
// ---------------------------------------------------------------------------
__global__ void prep_kernel(const float* __restrict__ eps,
                            const float* __restrict__ lam,
                            const float* __restrict__ eta,
                            const float* __restrict__ w,
                            float4* __restrict__ out) {
    int idx = blockIdx.x * blockDim.x + threadIdx.x;
    if (idx < B_HALF * D_DIM) {
        int b = idx >> 6;
        int j = idx & 63;
        float l = lam[j];
        float s = eps[idx] / (TWO_PI * l);
        __nv_bfloat16 sh = __float2bfloat16(s);
        g_Shi[idx] = sh;
        g_Slo[idx] = __float2bfloat16(s - __bfloat162float(sh));
        float eta2 = eta[0] * eta[0];
        float m;
        if (j < 32) {
            m = eps[b * 64 + 32 + j] / lam[32 + j];
        } else {
            m = -eps[b * 64 + (j - 32)] / lam[j - 32] - eta2 * eps[idx] / l;
        }
        __nv_bfloat16 mh = __float2bfloat16(m);
        g_Mthi[j * B_HALF + b] = mh;
        g_Mtlo[j * B_HALF + b] = __float2bfloat16(m - __bfloat162float(mh));
    }
    if (idx < B_HALF) {
        float ws = -(w[idx] + w[idx + B_HALF]);
        float wc = w[2 * B_HALF + idx] - w[3 * B_HALF + idx];
        g_R[idx] = sqrtf(ws * ws + wc * wc);
        g_P[idx] = atan2f(wc, ws) * INV_TWO_PI;
    }
    out[idx]         = make_float4(0.f, 0.f, 0.f, 0.f);
    out[idx + 65536] = make_float4(0.f, 0.f, 0.f, 0.f);
}

// ---------------------------------------------------------------------------
// Main kernel: warp-level bf16 MMA (m16n8k16) with ldmatrix fragment loads,
// split precision (3 MMAs per product). Block = 128 rows x 64 basis
// (grid 64 x 16); REDG merges basis groups into d_out.
// ---------------------------------------------------------------------------
__global__ void __launch_bounds__(TBM, 3)
main_kernel(const float* __restrict__ x, float* __restrict__ out) {
    extern __shared__ char smem[];
    const u32 sb = smem_to_u32(smem);
    u32* xhi32 = (u32*)(smem + OFF_XHI);   // [128][36 u32]
    u32* xlo32 = (u32*)(smem + OFF_XLO);
    u32* shi32 = (u32*)(smem + OFF_SHI);   // [64][36 u32]
    u32* slo32 = (u32*)(smem + OFF_SLO);
    u32* mth32 = (u32*)(smem + OFF_MTH);
    u32* mtl32 = (u32*)(smem + OFF_MTL);
    float* sR  = (float*)(smem + OFF_R);
    float* sP  = (float*)(smem + OFF_P);
    u32* uhi32 = xhi32;                    // U tile aliases X tile (phase B)
    u32* ulo32 = xlo32;

    const int tid  = threadIdx.x;
    const int lane = tid & 31;
    const int wr   = (tid >> 5) * 16;      // warp's first row
    const int g    = lane >> 2;            // 0..7
    const int t    = lane & 3;             // 0..3
    const int quad = lane >> 3;            // 0..3 (ldmatrix address role)
    const int qr   = lane & 7;
    const int bx   = blockIdx.x;
    const int b0   = blockIdx.y * 64;

    // ---- Stage X (f32 -> bf16 hi/lo), S, Mt tiles, R/phi ----
    {
        const float2* xg = (const float2*)(x + (size_t)bx * 128 * D_DIM);
        #pragma unroll
        for (int it = 0; it < 16; ++it) {
            int i   = tid + it * TBM;      // pair id, 4096 total
            int row = i >> 5;
            int kp  = i & 31;
            float2 v = xg[i];
            __nv_bfloat16 h0 = __float2bfloat16(v.x);
            __nv_bfloat16 h1 = __float2bfloat16(v.y);
            float l0 = v.x - __bfloat162float(h0);
            float l1 = v.y - __bfloat162float(h1);
            xhi32[row * 36 + kp] =
                (u32)__bfloat16_as_ushort(h0) | ((u32)__bfloat16_as_ushort(h1) << 16);
            xlo32[row * 36 + kp] = pack_bf16(l0, l1);
        }
        const u32* gShi = (const u32*)g_Shi;
        const u32* gSlo = (const u32*)g_Slo;
        const u32* gMth = (const u32*)g_Mthi;
        const u32* gMtl = (const u32*)g_Mtlo;
        #pragma unroll
        for (int it = 0; it < 8; ++it) {
            int i = tid + it * TBM;        // pair id, 2048 total
            int r = i >> 5;
            int p = i & 31;
            shi32[r * 36 + p] = gShi[(b0 + r) * 32 + p];
            slo32[r * 36 + p] = gSlo[(b0 + r) * 32 + p];
            mth32[r * 36 + p] = gMth[r * 512 + (b0 >> 1) + p];
            mtl32[r * 36 + p] = gMtl[r * 512 + (b0 >> 1) + p];
        }
        if (tid < 64) {
            sR[tid] = g_R[b0 + tid];
            sP[tid] = g_P[b0 + tid];
        }
    }

    // ---- Per-lane ldmatrix base addresses (bytes) ----
    // A x4 tiles: M0 rows m0-7 (k lo), M1 rows m8-15 (k lo), M2 m0-7 (k hi), M3 m8-15 (k hi)
    const int arow  = wr + ((quad & 1) << 3) + qr;
    const int acol4 = (quad >> 1) << 2;              // u32 col
    const u32 aHiB = sb + OFF_XHI + (u32)(arow * 36 + acol4) * 4;
    const u32 aLoB = aHiB + (OFF_XLO - OFF_XHI);
    // B x4 tiles for n-tile pair q: M0 rows n=16q+0..7 (k lo), M1 same rows (k hi),
    //                               M2 rows n=16q+8..15 (k lo), M3 same (k hi)
    const int brow  = ((quad >> 1) << 3) + qr;
    const int bcol4 = (quad & 1) << 2;
    const u32 bHiSB = sb + OFF_SHI + (u32)(brow * 36 + bcol4) * 4;
    const u32 bLoSB = bHiSB + (OFF_SLO - OFF_SHI);
    const u32 bHiMB = sb + OFF_MTH + (u32)(brow * 36 + bcol4) * 4;
    const u32 bLoMB = bHiMB + (OFF_MTL - OFF_MTH);

    __syncthreads();

    // ---- Phase A: P = Xhi@Shi^T + Xlo@Shi^T + Xhi@Slo^T ----
    float pA[8][4];
    #pragma unroll
    for (int nt = 0; nt < 8; ++nt)
        #pragma unroll
        for (int c = 0; c < 4; ++c) pA[nt][c] = 0.0f;

    #pragma unroll
    for (int ks = 0; ks < 4; ++ks) {
        u32 ah[4], al[4];
        LDSM_X4(ah, aHiB + ks * 32);
        LDSM_X4(al, aLoB + ks * 32);
        #pragma unroll
        for (int q = 0; q < 4; ++q) {
            u32 bh[4], bl[4];
            LDSM_X4(bh, bHiSB + q * 2304 + ks * 32);   // 16*36*4 = 2304
            LDSM_X4(bl, bLoSB + q * 2304 + ks * 32);
            MMA_BF16(pA[2*q],     ah, bh);
            MMA_BF16(pA[2*q],     al, bh);
            MMA_BF16(pA[2*q],     ah, bl);
            MMA_BF16(pA[2*q + 1], ah, bh + 2);
            MMA_BF16(pA[2*q + 1], al, bh + 2);
            MMA_BF16(pA[2*q + 1], ah, bl + 2);
        }
    }
    __syncthreads();   // all phase-A smem reads done before U aliases X

    // ---- Epilogue: u = R*sin(2*pi*frac(p + phi)); split bf16 -> U tile ----
    #pragma unroll
    for (int nt = 0; nt < 8; ++nt) {
        int c0 = nt * 8 + 2 * t;
        float R0 = sR[c0], R1 = sR[c0 + 1];
        float P0 = sP[c0], P1 = sP[c0 + 1];
        float p00 = pA[nt][0] + P0, p01 = pA[nt][1] + P1;
        float p10 = pA[nt][2] + P0, p11 = pA[nt][3] + P1;
        float u00 = R0 * __sinf((p00 - rintf(p00)) * TWO_PI);
        float u01 = R1 * __sinf((p01 - rintf(p01)) * TWO_PI);
        float u10 = R0 * __sinf((p10 - rintf(p10)) * TWO_PI);
        float u11 = R1 * __sinf((p11 - rintf(p11)) * TWO_PI);
        __nv_bfloat16 h00 = __float2bfloat16(u00);
        __nv_bfloat16 h01 = __float2bfloat16(u01);
        __nv_bfloat16 h10 = __float2bfloat16(u10);
        __nv_bfloat16 h11 = __float2bfloat16(u11);
        int ilo = (wr + g) * 36 + nt * 4 + t;
        int ihi = (wr + g + 8) * 36 + nt * 4 + t;
        uhi32[ilo] = (u32)__bfloat16_as_ushort(h00) | ((u32)__bfloat16_as_ushort(h01) << 16);
        uhi32[ihi] = (u32)__bfloat16_as_ushort(h10) | ((u32)__bfloat16_as_ushort(h11) << 16);
        ulo32[ilo] = pack_bf16(u00 - __bfloat162float(h00), u01 - __bfloat162float(h01));
        ulo32[ihi] = pack_bf16(u10 - __bfloat162float(h10), u11 - __bfloat162float(h11));
    }
    __syncthreads();

    // ---- Phase B: F = Uhi@Mthi^T + Ulo@Mthi^T + Uhi@Mtlo^T ----
    float fB[8][4];
    #pragma unroll
    for (int nt = 0; nt < 8; ++nt)
        #pragma unroll
        for (int c = 0; c < 4; ++c) fB[nt][c] = 0.0f;

    #pragma unroll
    for (int ks = 0; ks < 4; ++ks) {
        u32 ah[4], al[4];
        LDSM_X4(ah, aHiB + ks * 32);   // U aliases X region
        LDSM_X4(al, aLoB + ks * 32);
        #pragma unroll
        for (int q = 0; q < 4; ++q) {
            u32 bh[4], bl[4];
            LDSM_X4(bh, bHiMB + q * 2304 + ks * 32);
            LDSM_X4(bl, bLoMB + q * 2304 + ks * 32);
            MMA_BF16(fB[2*q],     ah, bh);
            MMA_BF16(fB[2*q],     al, bh);
            MMA_BF16(fB[2*q],     ah, bl);
            MMA_BF16(fB[2*q + 1], ah, bh + 2);
            MMA_BF16(fB[2*q + 1], al, bh + 2);
            MMA_BF16(fB[2*q + 1], ah, bl + 2);
        }
    }

    // ---- Accumulate into output via vector REDG ----
    {
        float* ob = out + (size_t)bx * 128 * D_DIM;
        #pragma unroll
        for (int nt = 0; nt < 8; ++nt) {
            int col = nt * 8 + 2 * t;
            float* plo = ob + (size_t)(wr + g) * D_DIM + col;
            float* phi = ob + (size_t)(wr + g + 8) * D_DIM + col;
            RED_ADD_V2(plo, fB[nt][0], fB[nt][1]);
            RED_ADD_V2(phi, fB[nt][2], fB[nt][3]);
        }
    }
}

// ---------------------------------------------------------------------------
extern "C" void kernel_launch(void* const* d_in, const int* in_sizes, int n_in,
                              void* d_out, int out_size) {
    const float* x   = nullptr;
    const float* eps = nullptr;
    const float* lam = nullptr;
    const float* eta = nullptr;
    const float* w   = nullptr;
    int ones_seen = 0;
    for (int i = 0; i < n_in; ++i) {
        int sz = in_sizes[i];
        const float* p = (const float*)d_in[i];
        if      (sz == N_ROWS * D_DIM)     x   = p;
        else if (sz == 2 * B_HALF * D_DIM) eps = p;
        else if (sz == D_DIM)              lam = p;
        else if (sz == 4 * B_HALF)         w   = p;
        else if (sz == 1) {
            if (ones_seen == 1) eta = p;   // second size-1 input is eta
            ones_seen++;
        }
    }

    cudaFuncSetAttribute(main_kernel,
                         cudaFuncAttributeMaxDynamicSharedMemorySize, SMEM_BYTES);

    prep_kernel<<<(B_HALF * D_DIM + 255) / 256, 256>>>(eps, lam, eta, w,
                                                       (float4*)d_out);
    main_kernel<<<dim3(N_ROWS / 128, B_HALF / 64), TBM, SMEM_BYTES>>>(
        x, (float*)d_out);
}